// round 7
// baseline (speedup 1.0000x reference)
#include <cuda_runtime.h>
#include <cuda_fp16.h>
#include <cstdint>

#define NQ 8192
#define NM 4096
#define ED 512
// log2(e) / TEMPERATURE  (TEMPERATURE = sqrt(512))
#define SM_SCALE (1.4426950408889634f / 22.627416997969522f)

// ---------------- scratch (__device__ globals; no allocs allowed) ----------
__device__ __half g_vch[NQ * ED];
__device__ __half g_och[NM * ED];
__device__ __half g_wall[3 * ED * ED];         // Wq | Wk | Wv rows
__device__ __half g_vqkv[(size_t)NQ * 3 * ED]; // vq|vk|vv per row (stride 1536)
__device__ __half g_okh[NM * ED];
__device__ __half g_ovT[(size_t)ED * NM];      // transposed V-proj of obs
__device__ __half g_P[(size_t)NQ * NM];        // softmax numerators (fp16)
__device__ float g_rs[(size_t)NQ * 16];        // per-(row, n-tile) partial P sums
__device__ float g_Opart[4][NQ * ED];          // split-K partials of O

// ---------------- helpers --------------------------------------------------
__device__ __forceinline__ uint32_t smem_u32(const void* p) {
    uint32_t a;
    asm("{ .reg .u64 t; cvta.to.shared.u64 t, %1; cvt.u32.u64 %0, t; }" : "=r"(a) : "l"(p));
    return a;
}

#define LDM4(r, addr) \
    asm volatile("ldmatrix.sync.aligned.m8n8.x4.shared.b16 {%0,%1,%2,%3}, [%4];" \
        : "=r"((r)[0]), "=r"((r)[1]), "=r"((r)[2]), "=r"((r)[3]) : "r"(addr))

// fp16 accumulate MMA
#define MMAH(d, a, b0, b1) \
    asm volatile("mma.sync.aligned.m16n8k16.row.col.f16.f16.f16.f16 " \
        "{%0,%1}, {%2,%3,%4,%5}, {%6,%7}, {%0,%1};" \
        : "+r"((d)[0]), "+r"((d)[1]) \
        : "r"((a)[0]), "r"((a)[1]), "r"((a)[2]), "r"((a)[3]), "r"(b0), "r"(b1))

// quartic exp2 on the FMA pipe (|rel err| < 5e-5 on the needed range)
__device__ __forceinline__ float fast_exp2(float x) {
    float t = x + 12582912.f;                 // round-to-nearest-int trick
    float fl = t - 12582912.f;
    float f = x - fl;                         // f in [-0.5, 0.5]
    int n = __float_as_int(t) - 0x4B400000;   // signed integer part
    float p = fmaf(fmaf(fmaf(fmaf(0.0096181291f, f, 0.0555041087f),
                             f, 0.2402265070f), f, 0.6931471806f), f, 1.0f);
    return __int_as_float(__float_as_int(p) + (n << 23));
}

// load A[128x64] + B[256x64] fp16 tiles into SW128-swizzled smem via cp.async
__device__ __forceinline__ void load_tiles_h(uint32_t ab, uint32_t bb,
    const __half* __restrict__ Ag, int lda,
    const __half* __restrict__ Bg, int ldb, int tid)
{
    int c  = tid & 7;
    int r0 = tid >> 3;
#pragma unroll
    for (int it = 0; it < 4; it++) {
        int row = r0 + it * 32;
        uint32_t off = (uint32_t)(row * 128 + ((c << 4) ^ ((row & 7) << 4)));
        asm volatile("cp.async.cg.shared.global [%0], [%1], 16;"
            :: "r"(ab + off), "l"(Ag + (size_t)row * lda + c * 8) : "memory");
    }
#pragma unroll
    for (int it = 0; it < 8; it++) {
        int row = r0 + it * 32;
        uint32_t off = (uint32_t)(row * 128 + ((c << 4) ^ ((row & 7) << 4)));
        asm volatile("cp.async.cg.shared.global [%0], [%1], 16;"
            :: "r"(bb + off), "l"(Bg + (size_t)row * ldb + c * 8) : "memory");
    }
    asm volatile("cp.async.commit_group;" ::: "memory");
}

// ---------------------------------------------------------------------------
// fp32 -> fp16 conversion of all inputs in ONE launch (weights concatenated)
// ---------------------------------------------------------------------------
__global__ __launch_bounds__(256) void cvt_all(
    const float4* __restrict__ vc, const float4* __restrict__ oc,
    const float4* __restrict__ wq, const float4* __restrict__ wk,
    const float4* __restrict__ wv)
{
    const int n_vc = NQ * ED / 4, n_oc = NM * ED / 4, n_w = ED * ED / 4;
    int i = blockIdx.x * 256 + threadIdx.x;
    const float4* s; uint2* d; int j;
    if (i < n_vc)                      { s = vc; d = (uint2*)g_vch;  j = i; }
    else if (i < n_vc + n_oc)          { s = oc; d = (uint2*)g_och;  j = i - n_vc; }
    else if (i < n_vc + n_oc + n_w)    { s = wq; d = (uint2*)g_wall; j = i - n_vc - n_oc; }
    else if (i < n_vc + n_oc + 2*n_w)  { s = wk; d = (uint2*)g_wall + n_w; j = i - n_vc - n_oc - n_w; }
    else if (i < n_vc + n_oc + 3*n_w)  { s = wv; d = (uint2*)g_wall + 2*n_w; j = i - n_vc - n_oc - 2*n_w; }
    else return;
    float4 v = s[j];
    __half2 a = __floats2half2_rn(v.x, v.y);
    __half2 b = __floats2half2_rn(v.z, v.w);
    d[j] = make_uint2(*(uint32_t*)&a, *(uint32_t*)&b);
}

// ---------------------------------------------------------------------------
// fp16 GEMM via mma.sync (f16 acc): D[128,256] = A[128,K] @ B[256,K]^T.
// 256 threads, warp grid 2(M) x 4(N), warp tile 64x64, BK=64, double buffered.
// mode 0: store fp16 row-major
// mode 1: exp2(x*SM_SCALE)->fp16 row-major + per-row partial sums -> g_rs
// mode 2: store fp32 row-major (split-K partial)
// mode 4: obs fused: n<512 -> g_okh normal; n>=512 -> g_ovT transposed
// nsy: #n-tiles in gridDim.y; blocks beyond that are split-K slices.
// ---------------------------------------------------------------------------
__global__ __launch_bounds__(256) void gemm_h(
    const __half* __restrict__ A, int lda,
    const __half* __restrict__ B, int ldb,
    void* __restrict__ C, int ldc, int K, int mode, int nsy)
{
    extern __shared__ char smem_raw[];
    uint32_t sb = smem_u32(smem_raw);

    const int tid = threadIdx.x;
    const int lane = tid & 31, wid = tid >> 5;
    const int wm = wid >> 2, wn = wid & 3;       // warp grid 2(M) x 4(N)
    const int split = blockIdx.y / nsy;
    const int bm = blockIdx.x * 128, bn = (blockIdx.y % nsy) * 256;
    const int nc = K >> 6;

    A += (size_t)split * K;                      // split-K column offset
    B += (size_t)split * K;
    float* Csplit = (float*)C + (size_t)split * ((size_t)gridDim.x * 128) * ldc;

    const __half* Abase = A + (size_t)bm * lda;
    const __half* Bbase = B + (size_t)bn * ldb;

    load_tiles_h(sb, sb + 16384, Abase, lda, Bbase, ldb, tid);
    if (nc > 1)
        load_tiles_h(sb + 49152, sb + 65536, Abase + 64, lda, Bbase + 64, ldb, tid);

    uint32_t acc[4][8][2];
#pragma unroll
    for (int i = 0; i < 4; i++)
#pragma unroll
        for (int j = 0; j < 8; j++) { acc[i][j][0] = 0u; acc[i][j][1] = 0u; }

    uint32_t a_rb[4], a_p[4], b_rb[4], b_p[4];
#pragma unroll
    for (int mi = 0; mi < 4; mi++) {
        int row = wm * 64 + mi * 16 + (lane & 15);
        a_rb[mi] = (uint32_t)(row * 128);
        a_p[mi]  = (uint32_t)((row & 7) << 4);
    }
#pragma unroll
    for (int nb = 0; nb < 4; nb++) {
        int row = wn * 64 + nb * 16 + (lane & 15);
        b_rb[nb] = (uint32_t)(row * 128);
        b_p[nb]  = (uint32_t)((row & 7) << 4);
    }
    const uint32_t h16 = (uint32_t)((lane >> 4) << 4);

    for (int i = 0; i < nc; i++) {
        int s = i & 1;
        if (i + 1 < nc) asm volatile("cp.async.wait_group 1;" ::: "memory");
        else            asm volatile("cp.async.wait_group 0;" ::: "memory");
        __syncthreads();

        uint32_t ab = sb + s * 49152;
        uint32_t bb = ab + 16384;
#pragma unroll
        for (int ks = 0; ks < 4; ks++) {
            uint32_t kh = (uint32_t)(ks << 5) | h16;
            uint32_t af[4][4], bf[4][4];
#pragma unroll
            for (int mi = 0; mi < 4; mi++)
                LDM4(af[mi], ab + a_rb[mi] + (kh ^ a_p[mi]));
#pragma unroll
            for (int nb = 0; nb < 4; nb++)
                LDM4(bf[nb], bb + b_rb[nb] + (kh ^ b_p[nb]));
#pragma unroll
            for (int mi = 0; mi < 4; mi++) {
#pragma unroll
                for (int nb = 0; nb < 4; nb++) {
                    MMAH(acc[mi][nb * 2 + 0], af[mi], bf[nb][0], bf[nb][2]);
                    MMAH(acc[mi][nb * 2 + 1], af[mi], bf[nb][1], bf[nb][3]);
                }
            }
        }
        __syncthreads();
        if (i + 2 < nc)
            load_tiles_h(ab, bb, Abase + (i + 2) * 64, lda, Bbase + (i + 2) * 64, ldb, tid);
    }

    // ---- epilogue straight from registers ---------------------------------
    const int g = lane >> 2, tg = lane & 3;
    float rs[4][2];
#pragma unroll
    for (int mi = 0; mi < 4; mi++) { rs[mi][0] = 0.f; rs[mi][1] = 0.f; }

#pragma unroll
    for (int mi = 0; mi < 4; mi++) {
#pragma unroll
        for (int nj = 0; nj < 8; nj++) {
            int m0 = bm + wm * 64 + mi * 16 + g;
            int n0 = bn + wn * 64 + nj * 8 + tg * 2;
            if (mode == 0) {
                __half* Ch = (__half*)C;
                *(uint32_t*)(Ch + (size_t)m0 * ldc + n0)       = acc[mi][nj][0];
                *(uint32_t*)(Ch + (size_t)(m0 + 8) * ldc + n0) = acc[mi][nj][1];
            } else if (mode == 1) {
                __half* Ch = (__half*)C;
                float2 lo = __half22float2(*(__half2*)&acc[mi][nj][0]);
                float2 hi = __half22float2(*(__half2*)&acc[mi][nj][1]);
                float p0 = fast_exp2(lo.x * SM_SCALE);
                float p1 = fast_exp2(lo.y * SM_SCALE);
                float p2 = fast_exp2(hi.x * SM_SCALE);
                float p3 = fast_exp2(hi.y * SM_SCALE);
                rs[mi][0] += p0 + p1;
                rs[mi][1] += p2 + p3;
                __half2 q0 = __floats2half2_rn(p0, p1);
                __half2 q1 = __floats2half2_rn(p2, p3);
                *(uint32_t*)(Ch + (size_t)m0 * ldc + n0)       = *(uint32_t*)&q0;
                *(uint32_t*)(Ch + (size_t)(m0 + 8) * ldc + n0) = *(uint32_t*)&q1;
            } else if (mode == 2) {
                float2 lo = __half22float2(*(__half2*)&acc[mi][nj][0]);
                float2 hi = __half22float2(*(__half2*)&acc[mi][nj][1]);
                *(float2*)(Csplit + (size_t)m0 * ldc + n0)       = lo;
                *(float2*)(Csplit + (size_t)(m0 + 8) * ldc + n0) = hi;
            } else {               // mode 4: obs fused proj
                if (n0 < 512) {    // ok: normal fp16, ldc = 512
                    __half* Ch = g_okh;
                    *(uint32_t*)(Ch + (size_t)m0 * ED + n0)       = acc[mi][nj][0];
                    *(uint32_t*)(Ch + (size_t)(m0 + 8) * ED + n0) = acc[mi][nj][1];
                } else {           // ov: transposed into g_ovT[e][kv]
                    int e0 = n0 - 512;
                    __half2 h0 = *(__half2*)&acc[mi][nj][0];
                    __half2 h1 = *(__half2*)&acc[mi][nj][1];
                    g_ovT[(size_t)e0 * NM + m0]           = __low2half(h0);
                    g_ovT[(size_t)(e0 + 1) * NM + m0]     = __high2half(h0);
                    g_ovT[(size_t)e0 * NM + m0 + 8]       = __low2half(h1);
                    g_ovT[(size_t)(e0 + 1) * NM + m0 + 8] = __high2half(h1);
                }
            }
        }
    }

    // ---- mode 1: deterministic per-row partial sum reduction --------------
    if (mode == 1) {
#pragma unroll
        for (int mi = 0; mi < 4; mi++) {
#pragma unroll
            for (int h = 0; h < 2; h++) {
                rs[mi][h] += __shfl_xor_sync(0xffffffffu, rs[mi][h], 1);
                rs[mi][h] += __shfl_xor_sync(0xffffffffu, rs[mi][h], 2);
            }
        }
        float* ps = (float*)smem_raw;            // reuse tile smem (post final barrier)
        __syncthreads();
        if (tg == 0) {
#pragma unroll
            for (int mi = 0; mi < 4; mi++) {
                ps[wn * 128 + wm * 64 + mi * 16 + g]     = rs[mi][0];
                ps[wn * 128 + wm * 64 + mi * 16 + g + 8] = rs[mi][1];
            }
        }
        __syncthreads();
        if (tid < 128) {
            float v = ps[tid] + ps[128 + tid] + ps[256 + tid] + ps[384 + tid];
            g_rs[(size_t)(bm + tid) * 16 + (bn >> 8)] = v;
        }
    }
}

// ---------------------------------------------------------------------------
// Epilogue: combine row sums, self term, split-K combine, normalize,
// residual, layernorm. One warp per row.
// ---------------------------------------------------------------------------
__global__ __launch_bounds__(256) void epi_kernel(
    const float* __restrict__ v_code,
    const float* __restrict__ gamma,
    const float* __restrict__ beta,
    float* __restrict__ out)
{
    int warp = threadIdx.x >> 5, lane = threadIdx.x & 31;
    int r = blockIdx.x * 8 + warp;

    // P row sum from qk partials (one per 256-col n-tile)
    float s = (lane < 16) ? g_rs[(size_t)r * 16 + lane] : 0.f;
#pragma unroll
    for (int o = 16; o > 0; o >>= 1) s += __shfl_xor_sync(0xffffffffu, s, o);

    // self-attention score q . k (fp16 operands, fp32 math)
    const uint4* q4 = (const uint4*)(g_vqkv + (size_t)r * 1536);
    const uint4* k4 = (const uint4*)(g_vqkv + (size_t)r * 1536 + 512);
    float sd = 0.f;
#pragma unroll
    for (int t = 0; t < 2; t++) {
        uint4 uq = q4[lane + 32 * t], uk = k4[lane + 32 * t];
        const __half2* hq = (const __half2*)&uq;
        const __half2* hk = (const __half2*)&uk;
#pragma unroll
        for (int j = 0; j < 4; j++) {
            float2 a = __half22float2(hq[j]);
            float2 b = __half22float2(hk[j]);
            sd += a.x * b.x + a.y * b.y;
        }
    }
#pragma unroll
    for (int o = 16; o > 0; o >>= 1) sd += __shfl_xor_sync(0xffffffffu, sd, o);
    float pself = exp2f(sd * SM_SCALE);
    float linv = 1.f / (s + pself);

    const float* vc = v_code + (size_t)r * ED;
    const __half* vv = g_vqkv + (size_t)r * 1536 + 1024;

    float vals[16];
    float mu = 0.f;
#pragma unroll
    for (int t = 0; t < 16; t++) {
        int e = lane + 32 * t;
        size_t idx = (size_t)r * ED + e;
        float o4 = g_Opart[0][idx] + g_Opart[1][idx] + g_Opart[2][idx] + g_Opart[3][idx];
        float v = (o4 + pself * __half2float(vv[e])) * linv + vc[e];
        vals[t] = v; mu += v;
    }
#pragma unroll
    for (int o = 16; o > 0; o >>= 1) mu += __shfl_xor_sync(0xffffffffu, mu, o);
    mu *= (1.f / 512.f);
    float var = 0.f;
#pragma unroll
    for (int t = 0; t < 16; t++) { float d = vals[t] - mu; var += d * d; }
#pragma unroll
    for (int o = 16; o > 0; o >>= 1) var += __shfl_xor_sync(0xffffffffu, var, o);
    float rstd = rsqrtf(var * (1.f / 512.f) + 1e-6f);
#pragma unroll
    for (int t = 0; t < 16; t++) {
        int e = lane + 32 * t;
        out[(size_t)r * ED + e] = (vals[t] - mu) * rstd * gamma[e] + beta[e];
    }
}

// ---------------------------------------------------------------------------
extern "C" void kernel_launch(void* const* d_in, const int* in_sizes, int n_in,
                              void* d_out, int out_size)
{
    const float* v_code   = (const float*)d_in[0];
    const float* obs_code = (const float*)d_in[1];
    const float* Wq       = (const float*)d_in[2];
    const float* Wk       = (const float*)d_in[3];
    const float* Wv       = (const float*)d_in[4];
    const float* gamma    = (const float*)d_in[5];
    const float* beta     = (const float*)d_in[6];
    float* out = (float*)d_out;

    __half *vch, *och, *wall, *vqkv, *okh, *ovT, *P;
    float* Op;
    cudaGetSymbolAddress((void**)&vch,  g_vch);
    cudaGetSymbolAddress((void**)&och,  g_och);
    cudaGetSymbolAddress((void**)&wall, g_wall);
    cudaGetSymbolAddress((void**)&vqkv, g_vqkv);
    cudaGetSymbolAddress((void**)&okh,  g_okh);
    cudaGetSymbolAddress((void**)&ovT,  g_ovT);
    cudaGetSymbolAddress((void**)&P,    g_P);
    cudaGetSymbolAddress((void**)&Op,   g_Opart);

    const int smem = 98304;
    cudaFuncSetAttribute(gemm_h, cudaFuncAttributeMaxDynamicSharedMemorySize, smem);
    dim3 blk(256);

    // #0: one fused convert (weights concatenated into g_wall)
    int n_cvt = (NQ * ED + NM * ED + 3 * ED * ED) / 4;
    cvt_all<<<(n_cvt + 255) / 256, 256>>>((const float4*)v_code, (const float4*)obs_code,
                                          (const float4*)Wq, (const float4*)Wk, (const float4*)Wv);
    // #1: fused v_code projection -> g_vqkv [8192, 1536]
    gemm_h<<<dim3(NQ / 128, 6),  blk, smem>>>(vch, ED, wall, ED, vqkv, 3 * ED, ED, 0, 6);
    // #2: fused obs projection -> g_okh + g_ovT (weights Wk|Wv)
    gemm_h<<<dim3(NM / 128, 4),  blk, smem>>>(och, ED, wall + ED * ED, ED, nullptr, 0, ED, 4, 4);
    // #3: QK^T + fused exp + row-sum partials -> P (fp16), g_rs
    gemm_h<<<dim3(NQ / 128, 16), blk, smem>>>(vqkv, 3 * ED, okh, ED, P, NM, ED, 1, 16);
    // #4: P @ ovT^T -> O, split-K x4 (grid.y = 2 n-tiles x 4 splits)
    gemm_h<<<dim3(NQ / 128, 8),  blk, smem>>>(P, NM, ovT, NM, Op, ED, NM / 4, 2, 2);
    // #5: softmax-normalize + residual + layernorm
    epi_kernel<<<NQ / 8, blk>>>(v_code, gamma, beta, out);
}

// round 8
// speedup vs baseline: 1.1486x; 1.1486x over previous
#include <cuda_runtime.h>
#include <cuda_fp16.h>
#include <cstdint>

#define NQ 8192
#define NM 4096
#define ED 512
// log2(e) / TEMPERATURE  (TEMPERATURE = sqrt(512))
#define SM_SCALE (1.4426950408889634f / 22.627416997969522f)

// ---------------- scratch (__device__ globals; no allocs allowed) ----------
__device__ __half g_vch[NQ * ED];
__device__ __half g_och[NM * ED];
__device__ __half g_wall[3 * ED * ED];         // Wq | Wk | Wv rows
__device__ __half g_vqkv[(size_t)NQ * 3 * ED]; // vq|vk|vv per row (stride 1536)
__device__ __half g_okh[NM * ED];
__device__ __half g_ovT[(size_t)ED * NM];      // transposed V-proj of obs
__device__ __half g_P[(size_t)NQ * NM];        // softmax numerators (fp16)
__device__ float g_rs[(size_t)NQ * 32];        // per-(row, n-tile) partial P sums
__device__ float g_Opart[4][NQ * ED];          // split-K partials of O

// ---------------- helpers --------------------------------------------------
__device__ __forceinline__ uint32_t smem_u32(const void* p) {
    uint32_t a;
    asm("{ .reg .u64 t; cvta.to.shared.u64 t, %1; cvt.u32.u64 %0, t; }" : "=r"(a) : "l"(p));
    return a;
}

#define LDM4(r, addr) \
    asm volatile("ldmatrix.sync.aligned.m8n8.x4.shared.b16 {%0,%1,%2,%3}, [%4];" \
        : "=r"((r)[0]), "=r"((r)[1]), "=r"((r)[2]), "=r"((r)[3]) : "r"(addr))

// fp16 accumulate MMA
#define MMAH(d, a, b0, b1) \
    asm volatile("mma.sync.aligned.m16n8k16.row.col.f16.f16.f16.f16 " \
        "{%0,%1}, {%2,%3,%4,%5}, {%6,%7}, {%0,%1};" \
        : "+r"((d)[0]), "+r"((d)[1]) \
        : "r"((a)[0]), "r"((a)[1]), "r"((a)[2]), "r"((a)[3]), "r"(b0), "r"(b1))

// quartic exp2 on the FMA pipe (|rel err| < 5e-5 on the needed range)
__device__ __forceinline__ float fast_exp2(float x) {
    float t = x + 12582912.f;                 // round-to-nearest-int trick
    float fl = t - 12582912.f;
    float f = x - fl;                         // f in [-0.5, 0.5]
    int n = __float_as_int(t) - 0x4B400000;   // signed integer part
    float p = fmaf(fmaf(fmaf(fmaf(0.0096181291f, f, 0.0555041087f),
                             f, 0.2402265070f), f, 0.6931471806f), f, 1.0f);
    return __int_as_float(__float_as_int(p) + (n << 23));
}

// load one 128x64 fp16 tile pair (A,B) into SW128-swizzled smem via cp.async
__device__ __forceinline__ void load_tiles_h(uint32_t ab, uint32_t bb,
    const __half* __restrict__ Ag, int lda,
    const __half* __restrict__ Bg, int ldb, int tid)
{
    int c  = tid & 7;
    int r0 = tid >> 3;
#pragma unroll
    for (int it = 0; it < 4; it++) {
        int row = r0 + it * 32;
        uint32_t off = (uint32_t)(row * 128 + ((c << 4) ^ ((row & 7) << 4)));
        asm volatile("cp.async.cg.shared.global [%0], [%1], 16;"
            :: "r"(ab + off), "l"(Ag + (size_t)row * lda + c * 8) : "memory");
        asm volatile("cp.async.cg.shared.global [%0], [%1], 16;"
            :: "r"(bb + off), "l"(Bg + (size_t)row * ldb + c * 8) : "memory");
    }
    asm volatile("cp.async.commit_group;" ::: "memory");
}

// ---------------------------------------------------------------------------
// fp32 -> fp16 conversion of all inputs in ONE launch (weights concatenated)
// ---------------------------------------------------------------------------
__global__ __launch_bounds__(256) void cvt_all(
    const float4* __restrict__ vc, const float4* __restrict__ oc,
    const float4* __restrict__ wq, const float4* __restrict__ wk,
    const float4* __restrict__ wv)
{
    const int n_vc = NQ * ED / 4, n_oc = NM * ED / 4, n_w = ED * ED / 4;
    int i = blockIdx.x * 256 + threadIdx.x;
    const float4* s; uint2* d; int j;
    if (i < n_vc)                      { s = vc; d = (uint2*)g_vch;  j = i; }
    else if (i < n_vc + n_oc)          { s = oc; d = (uint2*)g_och;  j = i - n_vc; }
    else if (i < n_vc + n_oc + n_w)    { s = wq; d = (uint2*)g_wall; j = i - n_vc - n_oc; }
    else if (i < n_vc + n_oc + 2*n_w)  { s = wk; d = (uint2*)g_wall + n_w; j = i - n_vc - n_oc - n_w; }
    else if (i < n_vc + n_oc + 3*n_w)  { s = wv; d = (uint2*)g_wall + 2*n_w; j = i - n_vc - n_oc - 2*n_w; }
    else return;
    float4 v = s[j];
    __half2 a = __floats2half2_rn(v.x, v.y);
    __half2 b = __floats2half2_rn(v.z, v.w);
    d[j] = make_uint2(*(uint32_t*)&a, *(uint32_t*)&b);
}

// ---------------------------------------------------------------------------
// fp16 GEMM via mma.sync (f16 acc): D[128,128] = A[128,K] @ B[128,K]^T.
// 256 threads, warp grid 2x4, warp tile 64x32, BK=64, double buffered.
// Inner-loop LDSM addresses use the XOR-immediate identity:
//   addr(ks) = (buf + row*128 + (swz ^ h16)) ^ (ks<<5)   [buf 128-aligned]
// mode 0: store fp16 row-major
// mode 1: exp2(x*SM_SCALE)->fp16 row-major + per-row partial sums -> g_rs
// mode 2: store fp32 row-major (split-K partial)
// mode 4: obs fused: n<512 -> g_okh normal; n>=512 -> g_ovT transposed
// nsy: #n-tiles in gridDim.y; blocks beyond that are split-K slices.
// ---------------------------------------------------------------------------
__global__ __launch_bounds__(256, 3) void gemm_h(
    const __half* __restrict__ A, int lda,
    const __half* __restrict__ B, int ldb,
    void* __restrict__ C, int ldc, int K, int mode, int nsy)
{
    extern __shared__ char smem_raw[];
    uint32_t sb = (smem_u32(smem_raw) + 127u) & ~127u;   // 128-aligned

    const int tid = threadIdx.x;
    const int lane = tid & 31, wid = tid >> 5;
    const int wm = wid >> 2, wn = wid & 3;       // warp grid 2(M) x 4(N)
    const int split = blockIdx.y / nsy;
    const int bm = blockIdx.x * 128, bn = (blockIdx.y % nsy) * 128;
    const int nc = K >> 6;

    A += (size_t)split * K;                      // split-K column offset
    B += (size_t)split * K;
    float* Csplit = (float*)C + (size_t)split * ((size_t)gridDim.x * 128) * ldc;

    const __half* Abase = A + (size_t)bm * lda;
    const __half* Bbase = B + (size_t)bn * ldb;

    load_tiles_h(sb, sb + 16384, Abase, lda, Bbase, ldb, tid);
    if (nc > 1)
        load_tiles_h(sb + 32768, sb + 49152, Abase + 64, lda, Bbase + 64, ldb, tid);

    uint32_t acc[4][4][2];
#pragma unroll
    for (int i = 0; i < 4; i++)
#pragma unroll
        for (int j = 0; j < 4; j++) { acc[i][j][0] = 0u; acc[i][j][1] = 0u; }

    // ldmatrix base offsets (relative to buffer): row*128 + (rowswz ^ h16)
    const uint32_t h16 = (uint32_t)((lane >> 4) << 4);
    uint32_t A0rel[4], B0rel[2];
#pragma unroll
    for (int mi = 0; mi < 4; mi++) {
        int row = wm * 64 + mi * 16 + (lane & 15);
        A0rel[mi] = (uint32_t)(row * 128) | ((uint32_t)((row & 7) << 4) ^ h16);
    }
#pragma unroll
    for (int nb = 0; nb < 2; nb++) {
        int row = wn * 32 + nb * 16 + (lane & 15);
        B0rel[nb] = (uint32_t)(row * 128) | ((uint32_t)((row & 7) << 4) ^ h16);
    }

    for (int i = 0; i < nc; i++) {
        int s = i & 1;
        if (i + 1 < nc) asm volatile("cp.async.wait_group 1;" ::: "memory");
        else            asm volatile("cp.async.wait_group 0;" ::: "memory");
        __syncthreads();

        uint32_t ab = sb + s * 32768;
        uint32_t bb = ab + 16384;
        uint32_t a0[4], b0[2];
#pragma unroll
        for (int mi = 0; mi < 4; mi++) a0[mi] = ab + A0rel[mi];
#pragma unroll
        for (int nb = 0; nb < 2; nb++) b0[nb] = bb + B0rel[nb];

#pragma unroll
        for (int ks = 0; ks < 4; ks++) {
            const uint32_t kx = (uint32_t)(ks << 5);  // immediate XOR
            uint32_t af[4][4], bf[2][4];
#pragma unroll
            for (int mi = 0; mi < 4; mi++)
                LDM4(af[mi], a0[mi] ^ kx);
#pragma unroll
            for (int nb = 0; nb < 2; nb++)
                LDM4(bf[nb], b0[nb] ^ kx);
#pragma unroll
            for (int mi = 0; mi < 4; mi++) {
#pragma unroll
                for (int nb = 0; nb < 2; nb++) {
                    MMAH(acc[mi][nb * 2 + 0], af[mi], bf[nb][0], bf[nb][2]);
                    MMAH(acc[mi][nb * 2 + 1], af[mi], bf[nb][1], bf[nb][3]);
                }
            }
        }
        __syncthreads();
        if (i + 2 < nc)
            load_tiles_h(ab, bb, Abase + (i + 2) * 64, lda, Bbase + (i + 2) * 64, ldb, tid);
    }

    // ---- epilogue straight from registers ---------------------------------
    const int g = lane >> 2, tg = lane & 3;
    float rs[4][2];
#pragma unroll
    for (int mi = 0; mi < 4; mi++) { rs[mi][0] = 0.f; rs[mi][1] = 0.f; }

#pragma unroll
    for (int mi = 0; mi < 4; mi++) {
#pragma unroll
        for (int nj = 0; nj < 4; nj++) {
            int m0 = bm + wm * 64 + mi * 16 + g;
            int n0 = bn + wn * 32 + nj * 8 + tg * 2;
            if (mode == 0) {
                __half* Ch = (__half*)C;
                *(uint32_t*)(Ch + (size_t)m0 * ldc + n0)       = acc[mi][nj][0];
                *(uint32_t*)(Ch + (size_t)(m0 + 8) * ldc + n0) = acc[mi][nj][1];
            } else if (mode == 1) {
                __half* Ch = (__half*)C;
                float2 lo = __half22float2(*(__half2*)&acc[mi][nj][0]);
                float2 hi = __half22float2(*(__half2*)&acc[mi][nj][1]);
                float p0 = fast_exp2(lo.x * SM_SCALE);
                float p1 = fast_exp2(lo.y * SM_SCALE);
                float p2 = fast_exp2(hi.x * SM_SCALE);
                float p3 = fast_exp2(hi.y * SM_SCALE);
                rs[mi][0] += p0 + p1;
                rs[mi][1] += p2 + p3;
                __half2 q0 = __floats2half2_rn(p0, p1);
                __half2 q1 = __floats2half2_rn(p2, p3);
                *(uint32_t*)(Ch + (size_t)m0 * ldc + n0)       = *(uint32_t*)&q0;
                *(uint32_t*)(Ch + (size_t)(m0 + 8) * ldc + n0) = *(uint32_t*)&q1;
            } else if (mode == 2) {
                float2 lo = __half22float2(*(__half2*)&acc[mi][nj][0]);
                float2 hi = __half22float2(*(__half2*)&acc[mi][nj][1]);
                *(float2*)(Csplit + (size_t)m0 * ldc + n0)       = lo;
                *(float2*)(Csplit + (size_t)(m0 + 8) * ldc + n0) = hi;
            } else {               // mode 4: obs fused proj
                if (bn < 512) {    // ok: normal fp16, ldc = 512
                    __half* Ch = g_okh;
                    *(uint32_t*)(Ch + (size_t)m0 * ED + n0)       = acc[mi][nj][0];
                    *(uint32_t*)(Ch + (size_t)(m0 + 8) * ED + n0) = acc[mi][nj][1];
                } else {           // ov: transposed into g_ovT[e][kv]
                    int e0 = n0 - 512;
                    __half2 h0 = *(__half2*)&acc[mi][nj][0];
                    __half2 h1 = *(__half2*)&acc[mi][nj][1];
                    g_ovT[(size_t)e0 * NM + m0]           = __low2half(h0);
                    g_ovT[(size_t)(e0 + 1) * NM + m0]     = __high2half(h0);
                    g_ovT[(size_t)e0 * NM + m0 + 8]       = __low2half(h1);
                    g_ovT[(size_t)(e0 + 1) * NM + m0 + 8] = __high2half(h1);
                }
            }
        }
    }

    // ---- mode 1: deterministic per-row partial sum reduction --------------
    if (mode == 1) {
#pragma unroll
        for (int mi = 0; mi < 4; mi++) {
#pragma unroll
            for (int h = 0; h < 2; h++) {
                rs[mi][h] += __shfl_xor_sync(0xffffffffu, rs[mi][h], 1);
                rs[mi][h] += __shfl_xor_sync(0xffffffffu, rs[mi][h], 2);
            }
        }
        float* ps = (float*)smem_raw;            // reuse tile smem
        __syncthreads();
        if (tg == 0) {
#pragma unroll
            for (int mi = 0; mi < 4; mi++) {
                ps[wn * 128 + wm * 64 + mi * 16 + g]     = rs[mi][0];
                ps[wn * 128 + wm * 64 + mi * 16 + g + 8] = rs[mi][1];
            }
        }
        __syncthreads();
        if (tid < 128) {
            float v = ps[tid] + ps[128 + tid] + ps[256 + tid] + ps[384 + tid];
            g_rs[(size_t)(bm + tid) * 32 + (bn >> 7)] = v;
        }
    }
}

// ---------------------------------------------------------------------------
// Epilogue: combine row sums, self term, split-K combine, normalize,
// residual, layernorm. One warp per row.
// ---------------------------------------------------------------------------
__global__ __launch_bounds__(256) void epi_kernel(
    const float* __restrict__ v_code,
    const float* __restrict__ gamma,
    const float* __restrict__ beta,
    float* __restrict__ out)
{
    int warp = threadIdx.x >> 5, lane = threadIdx.x & 31;
    int r = blockIdx.x * 8 + warp;

    // P row sum from qk partials (one per 128-col n-tile)
    float s = g_rs[(size_t)r * 32 + lane];
#pragma unroll
    for (int o = 16; o > 0; o >>= 1) s += __shfl_xor_sync(0xffffffffu, s, o);

    // self-attention score q . k (fp16 operands, fp32 math)
    const uint4* q4 = (const uint4*)(g_vqkv + (size_t)r * 1536);
    const uint4* k4 = (const uint4*)(g_vqkv + (size_t)r * 1536 + 512);
    float sd = 0.f;
#pragma unroll
    for (int t = 0; t < 2; t++) {
        uint4 uq = q4[lane + 32 * t], uk = k4[lane + 32 * t];
        const __half2* hq = (const __half2*)&uq;
        const __half2* hk = (const __half2*)&uk;
#pragma unroll
        for (int j = 0; j < 4; j++) {
            float2 a = __half22float2(hq[j]);
            float2 b = __half22float2(hk[j]);
            sd += a.x * b.x + a.y * b.y;
        }
    }
#pragma unroll
    for (int o = 16; o > 0; o >>= 1) sd += __shfl_xor_sync(0xffffffffu, sd, o);
    float pself = exp2f(sd * SM_SCALE);
    float linv = 1.f / (s + pself);

    const float* vc = v_code + (size_t)r * ED;
    const __half* vv = g_vqkv + (size_t)r * 1536 + 1024;

    float vals[16];
    float mu = 0.f;
#pragma unroll
    for (int t = 0; t < 16; t++) {
        int e = lane + 32 * t;
        size_t idx = (size_t)r * ED + e;
        float o4 = g_Opart[0][idx] + g_Opart[1][idx] + g_Opart[2][idx] + g_Opart[3][idx];
        float v = (o4 + pself * __half2float(vv[e])) * linv + vc[e];
        vals[t] = v; mu += v;
    }
#pragma unroll
    for (int o = 16; o > 0; o >>= 1) mu += __shfl_xor_sync(0xffffffffu, mu, o);
    mu *= (1.f / 512.f);
    float var = 0.f;
#pragma unroll
    for (int t = 0; t < 16; t++) { float d = vals[t] - mu; var += d * d; }
#pragma unroll
    for (int o = 16; o > 0; o >>= 1) var += __shfl_xor_sync(0xffffffffu, var, o);
    float rstd = rsqrtf(var * (1.f / 512.f) + 1e-6f);
#pragma unroll
    for (int t = 0; t < 16; t++) {
        int e = lane + 32 * t;
        out[(size_t)r * ED + e] = (vals[t] - mu) * rstd * gamma[e] + beta[e];
    }
}

// ---------------------------------------------------------------------------
extern "C" void kernel_launch(void* const* d_in, const int* in_sizes, int n_in,
                              void* d_out, int out_size)
{
    const float* v_code   = (const float*)d_in[0];
    const float* obs_code = (const float*)d_in[1];
    const float* Wq       = (const float*)d_in[2];
    const float* Wk       = (const float*)d_in[3];
    const float* Wv       = (const float*)d_in[4];
    const float* gamma    = (const float*)d_in[5];
    const float* beta     = (const float*)d_in[6];
    float* out = (float*)d_out;

    __half *vch, *och, *wall, *vqkv, *okh, *ovT, *P;
    float* Op;
    cudaGetSymbolAddress((void**)&vch,  g_vch);
    cudaGetSymbolAddress((void**)&och,  g_och);
    cudaGetSymbolAddress((void**)&wall, g_wall);
    cudaGetSymbolAddress((void**)&vqkv, g_vqkv);
    cudaGetSymbolAddress((void**)&okh,  g_okh);
    cudaGetSymbolAddress((void**)&ovT,  g_ovT);
    cudaGetSymbolAddress((void**)&P,    g_P);
    cudaGetSymbolAddress((void**)&Op,   g_Opart);

    const int smem = 65536 + 128;
    cudaFuncSetAttribute(gemm_h, cudaFuncAttributeMaxDynamicSharedMemorySize, smem);
    dim3 blk(256);

    // #0: one fused convert (weights concatenated into g_wall)
    int n_cvt = (NQ * ED + NM * ED + 3 * ED * ED) / 4;
    cvt_all<<<(n_cvt + 255) / 256, 256>>>((const float4*)v_code, (const float4*)obs_code,
                                          (const float4*)Wq, (const float4*)Wk, (const float4*)Wv);
    // #1: fused v_code projection -> g_vqkv [8192, 1536]
    gemm_h<<<dim3(NQ / 128, 12), blk, smem>>>(vch, ED, wall, ED, vqkv, 3 * ED, ED, 0, 12);
    // #2: fused obs projection -> g_okh + g_ovT (weights Wk|Wv)
    gemm_h<<<dim3(NM / 128, 8),  blk, smem>>>(och, ED, wall + ED * ED, ED, nullptr, 0, ED, 4, 8);
    // #3: QK^T + fused exp + row-sum partials -> P (fp16), g_rs
    gemm_h<<<dim3(NQ / 128, 32), blk, smem>>>(vqkv, 3 * ED, okh, ED, P, NM, ED, 1, 32);
    // #4: P @ ovT^T -> O, split-K x4 (grid.y = 4 n-tiles x 4 splits)
    gemm_h<<<dim3(NQ / 128, 16), blk, smem>>>(P, NM, ovT, NM, Op, ED, NM / 4, 2, 4);
    // #5: softmax-normalize + residual + layernorm
    epi_kernel<<<NQ / 8, blk>>>(v_code, gamma, beta, out);
}

// round 10
// speedup vs baseline: 1.1755x; 1.0234x over previous
#include <cuda_runtime.h>
#include <cuda_fp16.h>
#include <cstdint>

#define NQ 8192
#define NM 4096
#define ED 512
// log2(e) / TEMPERATURE  (TEMPERATURE = sqrt(512))
#define SM_SCALE (1.4426950408889634f / 22.627416997969522f)

// ---------------- scratch (__device__ globals; no allocs allowed) ----------
__device__ __half g_vch[NQ * ED];
__device__ __half g_och[NM * ED];
__device__ __half g_wall[3 * ED * ED];         // Wq | Wk | Wv rows
__device__ __half g_vqkv[(size_t)NQ * 3 * ED]; // vq|vk|vv per row (stride 1536)
__device__ __half g_okh[NM * ED];
__device__ __half g_ovT[(size_t)ED * NM];      // transposed V-proj of obs
__device__ __half g_P[(size_t)NQ * NM];        // softmax numerators (fp16)
__device__ float g_rs[(size_t)NQ * 32];        // per-(row, n-tile) partial P sums
__device__ float g_Opart[4][NQ * ED];          // split-K partials of O

// ---------------- helpers --------------------------------------------------
__device__ __forceinline__ uint32_t smem_u32(const void* p) {
    uint32_t a;
    asm("{ .reg .u64 t; cvta.to.shared.u64 t, %1; cvt.u32.u64 %0, t; }" : "=r"(a) : "l"(p));
    return a;
}

#define LDM4(r, addr) \
    asm volatile("ldmatrix.sync.aligned.m8n8.x4.shared.b16 {%0,%1,%2,%3}, [%4];" \
        : "=r"((r)[0]), "=r"((r)[1]), "=r"((r)[2]), "=r"((r)[3]) : "r"(addr))

// fp16 accumulate MMA
#define MMAH(d, a, b0, b1) \
    asm volatile("mma.sync.aligned.m16n8k16.row.col.f16.f16.f16.f16 " \
        "{%0,%1}, {%2,%3,%4,%5}, {%6,%7}, {%0,%1};" \
        : "+r"((d)[0]), "+r"((d)[1]) \
        : "r"((a)[0]), "r"((a)[1]), "r"((a)[2]), "r"((a)[3]), "r"(b0), "r"(b1))

// quartic exp2 on the FMA pipe (|rel err| < 5e-5 on the needed range)
__device__ __forceinline__ float fast_exp2(float x) {
    float t = x + 12582912.f;                 // round-to-nearest-int trick
    float fl = t - 12582912.f;
    float f = x - fl;                         // f in [-0.5, 0.5]
    int n = __float_as_int(t) - 0x4B400000;   // signed integer part
    float p = fmaf(fmaf(fmaf(fmaf(0.0096181291f, f, 0.0555041087f),
                             f, 0.2402265070f), f, 0.6931471806f), f, 1.0f);
    return __int_as_float(__float_as_int(p) + (n << 23));
}

// load one 128x64 fp16 tile pair (A,B) into SW128-swizzled smem (128 threads)
__device__ __forceinline__ void load_tiles_h(uint32_t ab, uint32_t bb,
    const __half* __restrict__ Ag, int lda,
    const __half* __restrict__ Bg, int ldb, int tid)
{
    int c  = tid & 7;
    int r0 = tid >> 3;                        // 0..15
#pragma unroll
    for (int it = 0; it < 8; it++) {
        int row = r0 + it * 16;
        uint32_t off = (uint32_t)(row * 128 + ((c << 4) ^ ((row & 7) << 4)));
        asm volatile("cp.async.cg.shared.global [%0], [%1], 16;"
            :: "r"(ab + off), "l"(Ag + (size_t)row * lda + c * 8) : "memory");
        asm volatile("cp.async.cg.shared.global [%0], [%1], 16;"
            :: "r"(bb + off), "l"(Bg + (size_t)row * ldb + c * 8) : "memory");
    }
    asm volatile("cp.async.commit_group;" ::: "memory");
}

// ---------------------------------------------------------------------------
// fp32 -> fp16 conversion of all inputs in ONE launch (weights concatenated)
// ---------------------------------------------------------------------------
__global__ __launch_bounds__(256) void cvt_all(
    const float4* __restrict__ vc, const float4* __restrict__ oc,
    const float4* __restrict__ wq, const float4* __restrict__ wk,
    const float4* __restrict__ wv)
{
    const int n_vc = NQ * ED / 4, n_oc = NM * ED / 4, n_w = ED * ED / 4;
    int i = blockIdx.x * 256 + threadIdx.x;
    const float4* s; uint2* d; int j;
    if (i < n_vc)                      { s = vc; d = (uint2*)g_vch;  j = i; }
    else if (i < n_vc + n_oc)          { s = oc; d = (uint2*)g_och;  j = i - n_vc; }
    else if (i < n_vc + n_oc + n_w)    { s = wq; d = (uint2*)g_wall; j = i - n_vc - n_oc; }
    else if (i < n_vc + n_oc + 2*n_w)  { s = wk; d = (uint2*)g_wall + n_w; j = i - n_vc - n_oc - n_w; }
    else if (i < n_vc + n_oc + 3*n_w)  { s = wv; d = (uint2*)g_wall + 2*n_w; j = i - n_vc - n_oc - 2*n_w; }
    else return;
    float4 v = s[j];
    __half2 a = __floats2half2_rn(v.x, v.y);
    __half2 b = __floats2half2_rn(v.z, v.w);
    d[j] = make_uint2(*(uint32_t*)&a, *(uint32_t*)&b);
}

// ---------------------------------------------------------------------------
// fp16 GEMM via mma.sync (f16 acc): D[128,128] = A[128,K] @ B[128,K]^T.
// 128 threads, warp grid 2(M) x 2(N), warp tile 64x64, BK=64, double buffered.
// LDSM addresses: addr(ks) = base ^ (ks<<5)   [buffers 128-aligned]
// mode 0: store fp16 row-major
// mode 1: exp2(x*SM_SCALE)->fp16 row-major + per-row partial sums -> g_rs
// mode 2: store fp32 row-major (split-K partial)
// mode 4: obs fused: n<512 -> g_okh normal; n>=512 -> g_ovT transposed
// nsy: #n-tiles in gridDim.y; blocks beyond that are split-K slices.
// ---------------------------------------------------------------------------
__global__ __launch_bounds__(128, 3) void gemm_h(
    const __half* __restrict__ A, int lda,
    const __half* __restrict__ B, int ldb,
    void* __restrict__ C, int ldc, int K, int mode, int nsy)
{
    extern __shared__ char smem_raw[];
    uint32_t sb = (smem_u32(smem_raw) + 127u) & ~127u;   // 128-aligned

    const int tid = threadIdx.x;
    const int lane = tid & 31, wid = tid >> 5;
    const int wm = wid >> 1, wn = wid & 1;       // warp grid 2(M) x 2(N)
    const int split = blockIdx.y / nsy;
    const int bm = blockIdx.x * 128, bn = (blockIdx.y % nsy) * 128;
    const int nc = K >> 6;

    A += (size_t)split * K;                      // split-K column offset
    B += (size_t)split * K;
    float* Csplit = (float*)C + (size_t)split * ((size_t)gridDim.x * 128) * ldc;

    const __half* Abase = A + (size_t)bm * lda;
    const __half* Bbase = B + (size_t)bn * ldb;

    load_tiles_h(sb, sb + 16384, Abase, lda, Bbase, ldb, tid);
    if (nc > 1)
        load_tiles_h(sb + 32768, sb + 49152, Abase + 64, lda, Bbase + 64, ldb, tid);

    uint32_t acc[4][8][2];
#pragma unroll
    for (int i = 0; i < 4; i++)
#pragma unroll
        for (int j = 0; j < 8; j++) { acc[i][j][0] = 0u; acc[i][j][1] = 0u; }

    // ldmatrix base offsets (relative to buffer): row*128 + (rowswz ^ h16)
    const uint32_t h16 = (uint32_t)((lane >> 4) << 4);
    uint32_t A0rel[4], B0rel[4];
#pragma unroll
    for (int mi = 0; mi < 4; mi++) {
        int row = wm * 64 + mi * 16 + (lane & 15);
        A0rel[mi] = (uint32_t)(row * 128) | ((uint32_t)((row & 7) << 4) ^ h16);
    }
#pragma unroll
    for (int nb = 0; nb < 4; nb++) {
        int row = wn * 64 + nb * 16 + (lane & 15);
        B0rel[nb] = (uint32_t)(row * 128) | ((uint32_t)((row & 7) << 4) ^ h16);
    }

    for (int i = 0; i < nc; i++) {
        int s = i & 1;
        if (i + 1 < nc) asm volatile("cp.async.wait_group 1;" ::: "memory");
        else            asm volatile("cp.async.wait_group 0;" ::: "memory");
        __syncthreads();

        uint32_t ab = sb + s * 32768;
        uint32_t bb = ab + 16384;
        uint32_t a0[4], b0[4];
#pragma unroll
        for (int mi = 0; mi < 4; mi++) a0[mi] = ab + A0rel[mi];
#pragma unroll
        for (int nb = 0; nb < 4; nb++) b0[nb] = bb + B0rel[nb];

#pragma unroll
        for (int ks = 0; ks < 4; ks++) {
            const uint32_t kx = (uint32_t)(ks << 5);  // immediate XOR
            uint32_t af[4][4], bf[4][4];
#pragma unroll
            for (int mi = 0; mi < 4; mi++)
                LDM4(af[mi], a0[mi] ^ kx);
#pragma unroll
            for (int nb = 0; nb < 4; nb++)
                LDM4(bf[nb], b0[nb] ^ kx);
#pragma unroll
            for (int mi = 0; mi < 4; mi++) {
#pragma unroll
                for (int nb = 0; nb < 4; nb++) {
                    MMAH(acc[mi][nb * 2 + 0], af[mi], bf[nb][0], bf[nb][2]);
                    MMAH(acc[mi][nb * 2 + 1], af[mi], bf[nb][1], bf[nb][3]);
                }
            }
        }
        __syncthreads();
        if (i + 2 < nc)
            load_tiles_h(ab, bb, Abase + (i + 2) * 64, lda, Bbase + (i + 2) * 64, ldb, tid);
    }

    // ---- epilogue straight from registers ---------------------------------
    const int g = lane >> 2, tg = lane & 3;
    float rs[4][2];
#pragma unroll
    for (int mi = 0; mi < 4; mi++) { rs[mi][0] = 0.f; rs[mi][1] = 0.f; }

#pragma unroll
    for (int mi = 0; mi < 4; mi++) {
#pragma unroll
        for (int nj = 0; nj < 8; nj++) {
            int m0 = bm + wm * 64 + mi * 16 + g;
            int n0 = bn + wn * 64 + nj * 8 + tg * 2;
            if (mode == 0) {
                __half* Ch = (__half*)C;
                *(uint32_t*)(Ch + (size_t)m0 * ldc + n0)       = acc[mi][nj][0];
                *(uint32_t*)(Ch + (size_t)(m0 + 8) * ldc + n0) = acc[mi][nj][1];
            } else if (mode == 1) {
                __half* Ch = (__half*)C;
                float2 lo = __half22float2(*(__half2*)&acc[mi][nj][0]);
                float2 hi = __half22float2(*(__half2*)&acc[mi][nj][1]);
                float p0 = fast_exp2(lo.x * SM_SCALE);
                float p1 = fast_exp2(lo.y * SM_SCALE);
                float p2 = fast_exp2(hi.x * SM_SCALE);
                float p3 = fast_exp2(hi.y * SM_SCALE);
                rs[mi][0] += p0 + p1;
                rs[mi][1] += p2 + p3;
                __half2 q0 = __floats2half2_rn(p0, p1);
                __half2 q1 = __floats2half2_rn(p2, p3);
                *(uint32_t*)(Ch + (size_t)m0 * ldc + n0)       = *(uint32_t*)&q0;
                *(uint32_t*)(Ch + (size_t)(m0 + 8) * ldc + n0) = *(uint32_t*)&q1;
            } else if (mode == 2) {
                float2 lo = __half22float2(*(__half2*)&acc[mi][nj][0]);
                float2 hi = __half22float2(*(__half2*)&acc[mi][nj][1]);
                *(float2*)(Csplit + (size_t)m0 * ldc + n0)       = lo;
                *(float2*)(Csplit + (size_t)(m0 + 8) * ldc + n0) = hi;
            } else {               // mode 4: obs fused proj
                if (n0 < 512) {    // ok: normal fp16, ldc = 512
                    __half* Ch = g_okh;
                    *(uint32_t*)(Ch + (size_t)m0 * ED + n0)       = acc[mi][nj][0];
                    *(uint32_t*)(Ch + (size_t)(m0 + 8) * ED + n0) = acc[mi][nj][1];
                } else {           // ov: transposed into g_ovT[e][kv]
                    int e0 = n0 - 512;
                    __half2 h0 = *(__half2*)&acc[mi][nj][0];
                    __half2 h1 = *(__half2*)&acc[mi][nj][1];
                    g_ovT[(size_t)e0 * NM + m0]           = __low2half(h0);
                    g_ovT[(size_t)(e0 + 1) * NM + m0]     = __high2half(h0);
                    g_ovT[(size_t)e0 * NM + m0 + 8]       = __low2half(h1);
                    g_ovT[(size_t)(e0 + 1) * NM + m0 + 8] = __high2half(h1);
                }
            }
        }
    }

    // ---- mode 1: deterministic per-row partial sum reduction --------------
    if (mode == 1) {
#pragma unroll
        for (int mi = 0; mi < 4; mi++) {
#pragma unroll
            for (int h = 0; h < 2; h++) {
                rs[mi][h] += __shfl_xor_sync(0xffffffffu, rs[mi][h], 1);
                rs[mi][h] += __shfl_xor_sync(0xffffffffu, rs[mi][h], 2);
            }
        }
        float* ps = (float*)smem_raw;            // reuse tile smem
        __syncthreads();
        if (tg == 0) {
#pragma unroll
            for (int mi = 0; mi < 4; mi++) {
                ps[wn * 128 + wm * 64 + mi * 16 + g]     = rs[mi][0];
                ps[wn * 128 + wm * 64 + mi * 16 + g + 8] = rs[mi][1];
            }
        }
        __syncthreads();
        {
            float v = ps[tid] + ps[128 + tid];
            g_rs[(size_t)(bm + tid) * 32 + (bn >> 7)] = v;
        }
    }
}

// ---------------------------------------------------------------------------
// Epilogue: combine row sums, self term, split-K combine, normalize,
// residual, layernorm. One warp per row, 8 warps (256 threads) per block.
// ---------------------------------------------------------------------------
__global__ __launch_bounds__(256) void epi_kernel(
    const float* __restrict__ v_code,
    const float* __restrict__ gamma,
    const float* __restrict__ beta,
    float* __restrict__ out)
{
    int warp = threadIdx.x >> 5, lane = threadIdx.x & 31;
    int r = blockIdx.x * 8 + warp;

    // P row sum from qk partials (one per 128-col n-tile)
    float s = g_rs[(size_t)r * 32 + lane];
#pragma unroll
    for (int o = 16; o > 0; o >>= 1) s += __shfl_xor_sync(0xffffffffu, s, o);

    // self-attention score q . k (fp16 operands, fp32 math)
    const uint4* q4 = (const uint4*)(g_vqkv + (size_t)r * 1536);
    const uint4* k4 = (const uint4*)(g_vqkv + (size_t)r * 1536 + 512);
    float sd = 0.f;
#pragma unroll
    for (int t = 0; t < 2; t++) {
        uint4 uq = q4[lane + 32 * t], uk = k4[lane + 32 * t];
        const __half2* hq = (const __half2*)&uq;
        const __half2* hk = (const __half2*)&uk;
#pragma unroll
        for (int j = 0; j < 4; j++) {
            float2 a = __half22float2(hq[j]);
            float2 b = __half22float2(hk[j]);
            sd += a.x * b.x + a.y * b.y;
        }
    }
#pragma unroll
    for (int o = 16; o > 0; o >>= 1) sd += __shfl_xor_sync(0xffffffffu, sd, o);
    float pself = exp2f(sd * SM_SCALE);
    float linv = 1.f / (s + pself);

    const float* vc = v_code + (size_t)r * ED;
    const __half* vv = g_vqkv + (size_t)r * 1536 + 1024;

    float vals[16];
    float mu = 0.f;
#pragma unroll
    for (int t = 0; t < 16; t++) {
        int e = lane + 32 * t;
        size_t idx = (size_t)r * ED + e;
        float o4 = g_Opart[0][idx] + g_Opart[1][idx] + g_Opart[2][idx] + g_Opart[3][idx];
        float v = (o4 + pself * __half2float(vv[e])) * linv + vc[e];
        vals[t] = v; mu += v;
    }
#pragma unroll
    for (int o = 16; o > 0; o >>= 1) mu += __shfl_xor_sync(0xffffffffu, mu, o);
    mu *= (1.f / 512.f);
    float var = 0.f;
#pragma unroll
    for (int t = 0; t < 16; t++) { float d = vals[t] - mu; var += d * d; }
#pragma unroll
    for (int o = 16; o > 0; o >>= 1) var += __shfl_xor_sync(0xffffffffu, var, o);
    float rstd = rsqrtf(var * (1.f / 512.f) + 1e-6f);
#pragma unroll
    for (int t = 0; t < 16; t++) {
        int e = lane + 32 * t;
        out[(size_t)r * ED + e] = (vals[t] - mu) * rstd * gamma[e] + beta[e];
    }
}

// ---------------------------------------------------------------------------
extern "C" void kernel_launch(void* const* d_in, const int* in_sizes, int n_in,
                              void* d_out, int out_size)
{
    const float* v_code   = (const float*)d_in[0];
    const float* obs_code = (const float*)d_in[1];
    const float* Wq       = (const float*)d_in[2];
    const float* Wk       = (const float*)d_in[3];
    const float* Wv       = (const float*)d_in[4];
    const float* gamma    = (const float*)d_in[5];
    const float* beta     = (const float*)d_in[6];
    float* out = (float*)d_out;

    __half *vch, *och, *wall, *vqkv, *okh, *ovT, *P;
    float* Op;
    cudaGetSymbolAddress((void**)&vch,  g_vch);
    cudaGetSymbolAddress((void**)&och,  g_och);
    cudaGetSymbolAddress((void**)&wall, g_wall);
    cudaGetSymbolAddress((void**)&vqkv, g_vqkv);
    cudaGetSymbolAddress((void**)&okh,  g_okh);
    cudaGetSymbolAddress((void**)&ovT,  g_ovT);
    cudaGetSymbolAddress((void**)&P,    g_P);
    cudaGetSymbolAddress((void**)&Op,   g_Opart);

    const int smem = 65536 + 128;
    cudaFuncSetAttribute(gemm_h, cudaFuncAttributeMaxDynamicSharedMemorySize, smem);
    dim3 gblk(128);   // GEMM blocks: 4 warps
    dim3 eblk(256);   // epilogue blocks: 8 warps (one per row)

    // #0: one fused convert (weights concatenated into g_wall)
    int n_cvt = (NQ * ED + NM * ED + 3 * ED * ED) / 4;
    cvt_all<<<(n_cvt + 255) / 256, 256>>>((const float4*)v_code, (const float4*)obs_code,
                                          (const float4*)Wq, (const float4*)Wk, (const float4*)Wv);
    // #1: fused v_code projection -> g_vqkv [8192, 1536]
    gemm_h<<<dim3(NQ / 128, 12), gblk, smem>>>(vch, ED, wall, ED, vqkv, 3 * ED, ED, 0, 12);
    // #2: fused obs projection -> g_okh + g_ovT (weights Wk|Wv)
    gemm_h<<<dim3(NM / 128, 8),  gblk, smem>>>(och, ED, wall + ED * ED, ED, nullptr, 0, ED, 4, 8);
    // #3: QK^T + fused exp + row-sum partials -> P (fp16), g_rs
    gemm_h<<<dim3(NQ / 128, 32), gblk, smem>>>(vqkv, 3 * ED, okh, ED, P, NM, ED, 1, 32);
    // #4: P @ ovT^T -> O, split-K x4 (grid.y = 4 n-tiles x 4 splits)
    gemm_h<<<dim3(NQ / 128, 16), gblk, smem>>>(P, NM, ovT, NM, Op, ED, NM / 4, 2, 4);
    // #5: softmax-normalize + residual + layernorm
    epi_kernel<<<NQ / 8, eblk>>>(v_code, gamma, beta, out);
}

// round 11
// speedup vs baseline: 1.1759x; 1.0003x over previous
#include <cuda_runtime.h>
#include <cuda_fp16.h>
#include <cstdint>

#define NQ 8192
#define NM 4096
#define ED 512
// log2(e) / TEMPERATURE  (TEMPERATURE = sqrt(512))
#define SM_SCALE (1.4426950408889634f / 22.627416997969522f)

// ---------------- scratch (__device__ globals; no allocs allowed) ----------
__device__ __half g_vch[NQ * ED];
__device__ __half g_och[NM * ED];
__device__ __half g_wall[3 * ED * ED];         // Wq | Wk | Wv rows
__device__ __half g_vqkv[(size_t)NQ * 3 * ED]; // vq|vk|vv per row (stride 1536)
__device__ __half g_okh[NM * ED];
__device__ __half g_ovT[(size_t)ED * NM];      // transposed V-proj of obs
__device__ __half g_P[(size_t)NQ * NM];        // softmax numerators (fp16)
__device__ float g_rs[(size_t)NQ * 32];        // per-(row, n-tile) partial P sums
__device__ float g_Opart[4][NQ * ED];          // split-K partials of O

// ---------------- helpers --------------------------------------------------
__device__ __forceinline__ uint32_t smem_u32(const void* p) {
    uint32_t a;
    asm("{ .reg .u64 t; cvta.to.shared.u64 t, %1; cvt.u32.u64 %0, t; }" : "=r"(a) : "l"(p));
    return a;
}

#define LDM4(r, addr) \
    asm volatile("ldmatrix.sync.aligned.m8n8.x4.shared.b16 {%0,%1,%2,%3}, [%4];" \
        : "=r"((r)[0]), "=r"((r)[1]), "=r"((r)[2]), "=r"((r)[3]) : "r"(addr))

// fp16 accumulate MMA
#define MMAH(d, a, b0, b1) \
    asm volatile("mma.sync.aligned.m16n8k16.row.col.f16.f16.f16.f16 " \
        "{%0,%1}, {%2,%3,%4,%5}, {%6,%7}, {%0,%1};" \
        : "+r"((d)[0]), "+r"((d)[1]) \
        : "r"((a)[0]), "r"((a)[1]), "r"((a)[2]), "r"((a)[3]), "r"(b0), "r"(b1))

// quartic exp2 on the FMA pipe (|rel err| < 5e-5 on the needed range)
__device__ __forceinline__ float fast_exp2(float x) {
    float t = x + 12582912.f;                 // round-to-nearest-int trick
    float fl = t - 12582912.f;
    float f = x - fl;                         // f in [-0.5, 0.5]
    int n = __float_as_int(t) - 0x4B400000;   // signed integer part
    float p = fmaf(fmaf(fmaf(fmaf(0.0096181291f, f, 0.0555041087f),
                             f, 0.2402265070f), f, 0.6931471806f), f, 1.0f);
    return __int_as_float(__float_as_int(p) + (n << 23));
}

// load one 128x64 fp16 tile pair (A,B) into SW128-swizzled smem (128 threads)
__device__ __forceinline__ void load_tiles_h(uint32_t ab, uint32_t bb,
    const __half* __restrict__ Ag, int lda,
    const __half* __restrict__ Bg, int ldb, int tid)
{
    int c  = tid & 7;
    int r0 = tid >> 3;                        // 0..15
#pragma unroll
    for (int it = 0; it < 8; it++) {
        int row = r0 + it * 16;
        uint32_t off = (uint32_t)(row * 128 + ((c << 4) ^ ((row & 7) << 4)));
        asm volatile("cp.async.cg.shared.global [%0], [%1], 16;"
            :: "r"(ab + off), "l"(Ag + (size_t)row * lda + c * 8) : "memory");
        asm volatile("cp.async.cg.shared.global [%0], [%1], 16;"
            :: "r"(bb + off), "l"(Bg + (size_t)row * ldb + c * 8) : "memory");
    }
    asm volatile("cp.async.commit_group;" ::: "memory");
}

// ---------------------------------------------------------------------------
// fp32 -> fp16 conversion of all inputs in ONE launch (weights concatenated)
// ---------------------------------------------------------------------------
__global__ __launch_bounds__(256) void cvt_all(
    const float4* __restrict__ vc, const float4* __restrict__ oc,
    const float4* __restrict__ wq, const float4* __restrict__ wk,
    const float4* __restrict__ wv)
{
    const int n_vc = NQ * ED / 4, n_oc = NM * ED / 4, n_w = ED * ED / 4;
    int i = blockIdx.x * 256 + threadIdx.x;
    const float4* s; uint2* d; int j;
    if (i < n_vc)                      { s = vc; d = (uint2*)g_vch;  j = i; }
    else if (i < n_vc + n_oc)          { s = oc; d = (uint2*)g_och;  j = i - n_vc; }
    else if (i < n_vc + n_oc + n_w)    { s = wq; d = (uint2*)g_wall; j = i - n_vc - n_oc; }
    else if (i < n_vc + n_oc + 2*n_w)  { s = wk; d = (uint2*)g_wall + n_w; j = i - n_vc - n_oc - n_w; }
    else if (i < n_vc + n_oc + 3*n_w)  { s = wv; d = (uint2*)g_wall + 2*n_w; j = i - n_vc - n_oc - 2*n_w; }
    else return;
    float4 v = s[j];
    __half2 a = __floats2half2_rn(v.x, v.y);
    __half2 b = __floats2half2_rn(v.z, v.w);
    d[j] = make_uint2(*(uint32_t*)&a, *(uint32_t*)&b);
}

// ---------------------------------------------------------------------------
// fp16 GEMM via mma.sync (f16 acc): D[128,128] = A[128,K] @ B[128,K]^T.
// 128 threads, warp grid 2(M) x 2(N), warp tile 64x64, BK=64, double buffered.
// LDSM addresses: addr(ks) = base ^ (ks<<5)   [buffers 128-aligned]
// mode 0: store fp16 row-major
// mode 1: exp2(x*SM_SCALE)->fp16 row-major + per-row partial sums -> g_rs
// mode 2: store fp32 row-major (split-K partial)
// mode 4: obs fused: n<512 -> g_okh normal; n>=512 -> g_ovT transposed
// bn0: n-tile offset (for n-sliced launches); split: explicit split-K index.
// ---------------------------------------------------------------------------
__global__ __launch_bounds__(128, 3) void gemm_h(
    const __half* __restrict__ A, int lda,
    const __half* __restrict__ B, int ldb,
    void* __restrict__ C, int ldc, int K, int mode, int bn0, int split)
{
    extern __shared__ char smem_raw[];
    uint32_t sb = (smem_u32(smem_raw) + 127u) & ~127u;   // 128-aligned

    const int tid = threadIdx.x;
    const int lane = tid & 31, wid = tid >> 5;
    const int wm = wid >> 1, wn = wid & 1;       // warp grid 2(M) x 2(N)
    const int bm = blockIdx.x * 128, bn = (bn0 + blockIdx.y) * 128;
    const int nc = K >> 6;

    A += (size_t)split * K;                      // split-K column offset
    B += (size_t)split * K;
    float* Csplit = (float*)C + (size_t)split * ((size_t)gridDim.x * 128) * ldc;

    const __half* Abase = A + (size_t)bm * lda;
    const __half* Bbase = B + (size_t)bn * ldb;

    load_tiles_h(sb, sb + 16384, Abase, lda, Bbase, ldb, tid);
    if (nc > 1)
        load_tiles_h(sb + 32768, sb + 49152, Abase + 64, lda, Bbase + 64, ldb, tid);

    uint32_t acc[4][8][2];
#pragma unroll
    for (int i = 0; i < 4; i++)
#pragma unroll
        for (int j = 0; j < 8; j++) { acc[i][j][0] = 0u; acc[i][j][1] = 0u; }

    // ldmatrix base offsets (relative to buffer): row*128 + (rowswz ^ h16)
    const uint32_t h16 = (uint32_t)((lane >> 4) << 4);
    uint32_t A0rel[4], B0rel[4];
#pragma unroll
    for (int mi = 0; mi < 4; mi++) {
        int row = wm * 64 + mi * 16 + (lane & 15);
        A0rel[mi] = (uint32_t)(row * 128) | ((uint32_t)((row & 7) << 4) ^ h16);
    }
#pragma unroll
    for (int nb = 0; nb < 4; nb++) {
        int row = wn * 64 + nb * 16 + (lane & 15);
        B0rel[nb] = (uint32_t)(row * 128) | ((uint32_t)((row & 7) << 4) ^ h16);
    }

    for (int i = 0; i < nc; i++) {
        int s = i & 1;
        if (i + 1 < nc) asm volatile("cp.async.wait_group 1;" ::: "memory");
        else            asm volatile("cp.async.wait_group 0;" ::: "memory");
        __syncthreads();

        uint32_t ab = sb + s * 32768;
        uint32_t bb = ab + 16384;
        uint32_t a0[4], b0[4];
#pragma unroll
        for (int mi = 0; mi < 4; mi++) a0[mi] = ab + A0rel[mi];
#pragma unroll
        for (int nb = 0; nb < 4; nb++) b0[nb] = bb + B0rel[nb];

#pragma unroll
        for (int ks = 0; ks < 4; ks++) {
            const uint32_t kx = (uint32_t)(ks << 5);  // immediate XOR
            uint32_t af[4][4], bf[4][4];
#pragma unroll
            for (int mi = 0; mi < 4; mi++)
                LDM4(af[mi], a0[mi] ^ kx);
#pragma unroll
            for (int nb = 0; nb < 4; nb++)
                LDM4(bf[nb], b0[nb] ^ kx);
#pragma unroll
            for (int mi = 0; mi < 4; mi++) {
#pragma unroll
                for (int nb = 0; nb < 4; nb++) {
                    MMAH(acc[mi][nb * 2 + 0], af[mi], bf[nb][0], bf[nb][2]);
                    MMAH(acc[mi][nb * 2 + 1], af[mi], bf[nb][1], bf[nb][3]);
                }
            }
        }
        __syncthreads();
        if (i + 2 < nc)
            load_tiles_h(ab, bb, Abase + (i + 2) * 64, lda, Bbase + (i + 2) * 64, ldb, tid);
    }

    // ---- epilogue straight from registers ---------------------------------
    const int g = lane >> 2, tg = lane & 3;
    float rs[4][2];
#pragma unroll
    for (int mi = 0; mi < 4; mi++) { rs[mi][0] = 0.f; rs[mi][1] = 0.f; }

#pragma unroll
    for (int mi = 0; mi < 4; mi++) {
#pragma unroll
        for (int nj = 0; nj < 8; nj++) {
            int m0 = bm + wm * 64 + mi * 16 + g;
            int n0 = bn + wn * 64 + nj * 8 + tg * 2;
            if (mode == 0) {
                __half* Ch = (__half*)C;
                *(uint32_t*)(Ch + (size_t)m0 * ldc + n0)       = acc[mi][nj][0];
                *(uint32_t*)(Ch + (size_t)(m0 + 8) * ldc + n0) = acc[mi][nj][1];
            } else if (mode == 1) {
                __half* Ch = (__half*)C;
                float2 lo = __half22float2(*(__half2*)&acc[mi][nj][0]);
                float2 hi = __half22float2(*(__half2*)&acc[mi][nj][1]);
                float p0 = fast_exp2(lo.x * SM_SCALE);
                float p1 = fast_exp2(lo.y * SM_SCALE);
                float p2 = fast_exp2(hi.x * SM_SCALE);
                float p3 = fast_exp2(hi.y * SM_SCALE);
                rs[mi][0] += p0 + p1;
                rs[mi][1] += p2 + p3;
                __half2 q0 = __floats2half2_rn(p0, p1);
                __half2 q1 = __floats2half2_rn(p2, p3);
                *(uint32_t*)(Ch + (size_t)m0 * ldc + n0)       = *(uint32_t*)&q0;
                *(uint32_t*)(Ch + (size_t)(m0 + 8) * ldc + n0) = *(uint32_t*)&q1;
            } else if (mode == 2) {
                float2 lo = __half22float2(*(__half2*)&acc[mi][nj][0]);
                float2 hi = __half22float2(*(__half2*)&acc[mi][nj][1]);
                *(float2*)(Csplit + (size_t)m0 * ldc + n0)       = lo;
                *(float2*)(Csplit + (size_t)(m0 + 8) * ldc + n0) = hi;
            } else {               // mode 4: obs fused proj
                if (n0 < 512) {    // ok: normal fp16, ldc = 512
                    __half* Ch = g_okh;
                    *(uint32_t*)(Ch + (size_t)m0 * ED + n0)       = acc[mi][nj][0];
                    *(uint32_t*)(Ch + (size_t)(m0 + 8) * ED + n0) = acc[mi][nj][1];
                } else {           // ov: transposed into g_ovT[e][kv]
                    int e0 = n0 - 512;
                    __half2 h0 = *(__half2*)&acc[mi][nj][0];
                    __half2 h1 = *(__half2*)&acc[mi][nj][1];
                    g_ovT[(size_t)e0 * NM + m0]           = __low2half(h0);
                    g_ovT[(size_t)(e0 + 1) * NM + m0]     = __high2half(h0);
                    g_ovT[(size_t)e0 * NM + m0 + 8]       = __low2half(h1);
                    g_ovT[(size_t)(e0 + 1) * NM + m0 + 8] = __high2half(h1);
                }
            }
        }
    }

    // ---- mode 1: deterministic per-row partial sum reduction --------------
    if (mode == 1) {
#pragma unroll
        for (int mi = 0; mi < 4; mi++) {
#pragma unroll
            for (int h = 0; h < 2; h++) {
                rs[mi][h] += __shfl_xor_sync(0xffffffffu, rs[mi][h], 1);
                rs[mi][h] += __shfl_xor_sync(0xffffffffu, rs[mi][h], 2);
            }
        }
        float* ps = (float*)smem_raw;            // reuse tile smem
        __syncthreads();
        if (tg == 0) {
#pragma unroll
            for (int mi = 0; mi < 4; mi++) {
                ps[wn * 128 + wm * 64 + mi * 16 + g]     = rs[mi][0];
                ps[wn * 128 + wm * 64 + mi * 16 + g + 8] = rs[mi][1];
            }
        }
        __syncthreads();
        {
            float v = ps[tid] + ps[128 + tid];
            g_rs[(size_t)(bm + tid) * 32 + (bn >> 7)] = v;
        }
    }
}

// ---------------------------------------------------------------------------
// Epilogue: combine row sums, self term, split-K combine, normalize,
// residual, layernorm. One warp per row, 8 warps (256 threads) per block.
// ---------------------------------------------------------------------------
__global__ __launch_bounds__(256) void epi_kernel(
    const float* __restrict__ v_code,
    const float* __restrict__ gamma,
    const float* __restrict__ beta,
    float* __restrict__ out)
{
    int warp = threadIdx.x >> 5, lane = threadIdx.x & 31;
    int r = blockIdx.x * 8 + warp;

    // P row sum from qk partials (one per 128-col n-tile)
    float s = g_rs[(size_t)r * 32 + lane];
#pragma unroll
    for (int o = 16; o > 0; o >>= 1) s += __shfl_xor_sync(0xffffffffu, s, o);

    // self-attention score q . k (fp16 operands, fp32 math)
    const uint4* q4 = (const uint4*)(g_vqkv + (size_t)r * 1536);
    const uint4* k4 = (const uint4*)(g_vqkv + (size_t)r * 1536 + 512);
    float sd = 0.f;
#pragma unroll
    for (int t = 0; t < 2; t++) {
        uint4 uq = q4[lane + 32 * t], uk = k4[lane + 32 * t];
        const __half2* hq = (const __half2*)&uq;
        const __half2* hk = (const __half2*)&uk;
#pragma unroll
        for (int j = 0; j < 4; j++) {
            float2 a = __half22float2(hq[j]);
            float2 b = __half22float2(hk[j]);
            sd += a.x * b.x + a.y * b.y;
        }
    }
#pragma unroll
    for (int o = 16; o > 0; o >>= 1) sd += __shfl_xor_sync(0xffffffffu, sd, o);
    float pself = exp2f(sd * SM_SCALE);
    float linv = 1.f / (s + pself);

    const float* vc = v_code + (size_t)r * ED;
    const __half* vv = g_vqkv + (size_t)r * 1536 + 1024;

    float vals[16];
    float mu = 0.f;
#pragma unroll
    for (int t = 0; t < 16; t++) {
        int e = lane + 32 * t;
        size_t idx = (size_t)r * ED + e;
        float o4 = g_Opart[0][idx] + g_Opart[1][idx] + g_Opart[2][idx] + g_Opart[3][idx];
        float v = (o4 + pself * __half2float(vv[e])) * linv + vc[e];
        vals[t] = v; mu += v;
    }
#pragma unroll
    for (int o = 16; o > 0; o >>= 1) mu += __shfl_xor_sync(0xffffffffu, mu, o);
    mu *= (1.f / 512.f);
    float var = 0.f;
#pragma unroll
    for (int t = 0; t < 16; t++) { float d = vals[t] - mu; var += d * d; }
#pragma unroll
    for (int o = 16; o > 0; o >>= 1) var += __shfl_xor_sync(0xffffffffu, var, o);
    float rstd = rsqrtf(var * (1.f / 512.f) + 1e-6f);
#pragma unroll
    for (int t = 0; t < 16; t++) {
        int e = lane + 32 * t;
        out[(size_t)r * ED + e] = (vals[t] - mu) * rstd * gamma[e] + beta[e];
    }
}

// ---------------------------------------------------------------------------
extern "C" void kernel_launch(void* const* d_in, const int* in_sizes, int n_in,
                              void* d_out, int out_size)
{
    const float* v_code   = (const float*)d_in[0];
    const float* obs_code = (const float*)d_in[1];
    const float* Wq       = (const float*)d_in[2];
    const float* Wk       = (const float*)d_in[3];
    const float* Wv       = (const float*)d_in[4];
    const float* gamma    = (const float*)d_in[5];
    const float* beta     = (const float*)d_in[6];
    float* out = (float*)d_out;

    __half *vch, *och, *wall, *vqkv, *okh, *ovT, *P;
    float* Op;
    cudaGetSymbolAddress((void**)&vch,  g_vch);
    cudaGetSymbolAddress((void**)&och,  g_och);
    cudaGetSymbolAddress((void**)&wall, g_wall);
    cudaGetSymbolAddress((void**)&vqkv, g_vqkv);
    cudaGetSymbolAddress((void**)&okh,  g_okh);
    cudaGetSymbolAddress((void**)&ovT,  g_ovT);
    cudaGetSymbolAddress((void**)&P,    g_P);
    cudaGetSymbolAddress((void**)&Op,   g_Opart);

    // lazy one-time side stream + events (host objects; no device allocs)
    static cudaStream_t s1 = nullptr;
    static cudaEvent_t evCvt, evP2, evQk[4], evPv;
    if (!s1) {
        cudaStreamCreateWithFlags(&s1, cudaStreamNonBlocking);
        cudaEventCreateWithFlags(&evCvt, cudaEventDisableTiming);
        cudaEventCreateWithFlags(&evP2,  cudaEventDisableTiming);
        for (int i = 0; i < 4; i++)
            cudaEventCreateWithFlags(&evQk[i], cudaEventDisableTiming);
        cudaEventCreateWithFlags(&evPv, cudaEventDisableTiming);
    }

    const int smem = 65536 + 128;
    static bool attr_set = false;
    if (!attr_set) {
        cudaFuncSetAttribute(gemm_h, cudaFuncAttributeMaxDynamicSharedMemorySize, smem);
        attr_set = true;
    }
    cudaFuncSetAttribute(gemm_h, cudaFuncAttributeMaxDynamicSharedMemorySize, smem);
    dim3 gblk(128);   // GEMM blocks: 4 warps
    dim3 eblk(256);   // epilogue blocks: 8 warps (one per row)

    // stream 0: cvt
    int n_cvt = (NQ * ED + NM * ED + 3 * ED * ED) / 4;
    cvt_all<<<(n_cvt + 255) / 256, 256>>>((const float4*)v_code, (const float4*)obs_code,
                                          (const float4*)Wq, (const float4*)Wk, (const float4*)Wv);
    cudaEventRecord(evCvt, 0);

    // s1: fused obs projection (parallel with proj1)
    cudaStreamWaitEvent(s1, evCvt, 0);
    gemm_h<<<dim3(NM / 128, 8), gblk, smem, s1>>>(och, ED, wall + ED * ED, ED,
                                                  nullptr, 0, ED, 4, 0, 0);
    cudaEventRecord(evP2, s1);

    // stream 0: fused v_code projection
    gemm_h<<<dim3(NQ / 128, 12), gblk, smem>>>(vch, ED, wall, ED, vqkv, 3 * ED, ED, 0, 0, 0);

    // stream 0: qk in 4 n-slices (each needs proj1 + proj2)
    cudaStreamWaitEvent(0, evP2, 0);
    for (int s = 0; s < 4; s++) {
        gemm_h<<<dim3(NQ / 128, 8), gblk, smem>>>(vqkv, 3 * ED, okh, ED, P, NM, ED, 1, 8 * s, 0);
        cudaEventRecord(evQk[s], 0);
    }

    // s1: pv split-K slices, each gated on its qk slice
    for (int s = 0; s < 4; s++) {
        cudaStreamWaitEvent(s1, evQk[s], 0);
        gemm_h<<<dim3(NQ / 128, 4), gblk, smem, s1>>>(P, NM, ovT, NM, Op, ED, NM / 4, 2, 0, s);
    }
    cudaEventRecord(evPv, s1);

    // stream 0: join + epilogue
    cudaStreamWaitEvent(0, evPv, 0);
    epi_kernel<<<NQ / 8, eblk>>>(v_code, gamma, beta, out);
}